// round 1
// baseline (speedup 1.0000x reference)
#include <cuda_runtime.h>
#include <cstdint>

// HashEmbedder: Instant-NGP multiresolution hash grid encoding.
// 524288 points, 16 levels, 2 features/level, 2^19-entry tables per level.
//
// out[b, l*2 + f] = trilinear interp of table[l][hash(corner)][f] over the 8
// corners of the voxel containing point b at level l's resolution.

#define NPOINTS_HINT 524288
#define N_LEVELS 16
#define LOG2T 19
#define TABLE_SZ (1u << LOG2T)
#define TMASK (TABLE_SZ - 1u)

// floor(16 * cbrt(2)^i) for i=0..15 (exact math; see analysis).
__device__ __constant__ float c_res[N_LEVELS] = {
    16.f, 20.f, 25.f, 32.f, 40.f, 50.f, 64.f, 80.f,
    101.f, 128.f, 161.f, 203.f, 256.f, 322.f, 406.f, 512.f
};

__device__ __forceinline__ float2 lerp2(float2 a, float2 b, float t) {
    float2 r;
    r.x = a.x + t * (b.x - a.x);
    r.y = a.y + t * (b.y - a.y);
    return r;
}

__global__ __launch_bounds__(256)
void hashgrid_kernel(const float* __restrict__ pts,
                     const float2* __restrict__ tables,
                     float2* __restrict__ out,
                     int n)
{
    int b = blockIdx.x * blockDim.x + threadIdx.x;
    if (b >= n) return;

    // point, shifted by -BOX_MIN = +1
    float ax = __ldg(pts + 3 * b + 0) + 1.0f;
    float ay = __ldg(pts + 3 * b + 1) + 1.0f;
    float az = __ldg(pts + 3 * b + 2) + 1.0f;

    const unsigned P0 = 73856093u, P1 = 19349663u, P2 = 83492791u;

    float2* o = out + (size_t)b * N_LEVELS;

#pragma unroll 4
    for (int l = 0; l < N_LEVELS; l++) {
        // grid = (BOX_MAX - BOX_MIN) / res, scaled = (p - BOX_MIN) / grid.
        // IEEE fp32 division both times to bit-match the XLA reference
        // (grid division folds at compile time; scaled division is IEEE '/').
        float grid = 2.0f / c_res[l];
        float sx = ax / grid;
        float sy = ay / grid;
        float sz = az / grid;

        float fx = floorf(sx), fy = floorf(sy), fz = floorf(sz);
        float wx = sx - fx, wy = sy - fy, wz = sz - fz;

        unsigned ix = (unsigned)(int)fx;
        unsigned iy = (unsigned)(int)fy;
        unsigned iz = (unsigned)(int)fz;

        // corner hash products: (c+1)*P == c*P + P
        unsigned hx0 = ix * P0, hx1 = hx0 + P0;
        unsigned hy0 = iy * P1, hy1 = hy0 + P1;
        unsigned hz0 = iz * P2, hz1 = hz0 + P2;

        const float2* t = tables + (size_t)l * TABLE_SZ;

        // 8 independent gathers (offsets order: i outer, j, k inner)
        float2 c000 = __ldg(t + ((hx0 ^ hy0 ^ hz0) & TMASK));
        float2 c001 = __ldg(t + ((hx0 ^ hy0 ^ hz1) & TMASK));
        float2 c010 = __ldg(t + ((hx0 ^ hy1 ^ hz0) & TMASK));
        float2 c011 = __ldg(t + ((hx0 ^ hy1 ^ hz1) & TMASK));
        float2 c100 = __ldg(t + ((hx1 ^ hy0 ^ hz0) & TMASK));
        float2 c101 = __ldg(t + ((hx1 ^ hy0 ^ hz1) & TMASK));
        float2 c110 = __ldg(t + ((hx1 ^ hy1 ^ hz0) & TMASK));
        float2 c111 = __ldg(t + ((hx1 ^ hy1 ^ hz1) & TMASK));

        // trilinear: lerp z, then y, then x
        float2 c00 = lerp2(c000, c001, wz);
        float2 c01 = lerp2(c010, c011, wz);
        float2 c10 = lerp2(c100, c101, wz);
        float2 c11 = lerp2(c110, c111, wz);
        float2 c0  = lerp2(c00, c01, wy);
        float2 c1  = lerp2(c10, c11, wy);
        float2 r   = lerp2(c0, c1, wx);

        o[l] = r;
    }
}

extern "C" void kernel_launch(void* const* d_in, const int* in_sizes, int n_in,
                              void* d_out, int out_size)
{
    const float*  pts    = (const float*)d_in[0];          // [n, 3]
    const float2* tables = (const float2*)d_in[1];         // [16, 2^19, 2] as float2
    float2*       out    = (float2*)d_out;                 // [n, 16] float2

    int n = in_sizes[0] / 3;
    int threads = 256;
    int blocks = (n + threads - 1) / threads;
    hashgrid_kernel<<<blocks, threads>>>(pts, tables, out, n);
}

// round 2
// speedup vs baseline: 1.3679x; 1.3679x over previous
#include <cuda_runtime.h>
#include <cstdint>

// HashEmbedder: Instant-NGP multiresolution hash grid encoding.
// Round 2: Morton-bin spatial sort of the points so warps are spatially
// coherent -> L1tex coalesces duplicate corner gathers at coarse/mid levels
// (wavefront-bound kernel per R1 ncu: L1=86.6%). Plus register-accumulated
// float4 output stores.

#define MAXPTS    524288
#define NBINS_DIM 32
#define NBINS     (NBINS_DIM * NBINS_DIM * NBINS_DIM)
#define N_LEVELS  16
#define TABLE_SZ  (1u << 19)
#define TMASK     (TABLE_SZ - 1u)

// scratch (no allocations allowed)
__device__ unsigned g_count[NBINS];
__device__ unsigned g_offset[NBINS];
__device__ float4   g_sorted[MAXPTS];   // xyz + original index (as int bits)

// floor(16 * cbrt(2)^i) for i=0..15
__device__ __constant__ float c_res[N_LEVELS] = {
    16.f, 20.f, 25.f, 32.f, 40.f, 50.f, 64.f, 80.f,
    101.f, 128.f, 161.f, 203.f, 256.f, 322.f, 406.f, 512.f
};

__device__ __forceinline__ unsigned part1by2(unsigned x) {
    x &= 0x3FF;
    x = (x | (x << 16)) & 0x030000FF;
    x = (x | (x << 8))  & 0x0300F00F;
    x = (x | (x << 4))  & 0x030C30C3;
    x = (x | (x << 2))  & 0x09249249;
    return x;
}

__device__ __forceinline__ unsigned bin_of(float x, float y, float z) {
    // box [-1,1] -> 32^3 cells; inputs are within +-0.95 but clamp anyway
    int cx = (int)((x + 1.0f) * 16.0f);
    int cy = (int)((y + 1.0f) * 16.0f);
    int cz = (int)((z + 1.0f) * 16.0f);
    cx = min(max(cx, 0), 31);
    cy = min(max(cy, 0), 31);
    cz = min(max(cz, 0), 31);
    return part1by2((unsigned)cx) | (part1by2((unsigned)cy) << 1) |
           (part1by2((unsigned)cz) << 2);
}

__global__ void zero_bins_kernel() {
    int i = blockIdx.x * blockDim.x + threadIdx.x;
    if (i < NBINS) g_count[i] = 0;
}

__global__ void count_kernel(const float* __restrict__ pts, int n) {
    int i = blockIdx.x * blockDim.x + threadIdx.x;
    if (i >= n) return;
    float x = pts[3 * i + 0], y = pts[3 * i + 1], z = pts[3 * i + 2];
    atomicAdd(&g_count[bin_of(x, y, z)], 1u);
}

// single-block exclusive scan over 32768 bins (1024 threads x 32 each)
__global__ __launch_bounds__(1024)
void scan_kernel() {
    __shared__ unsigned sh[1024];
    int t = threadIdx.x;
    unsigned v[32];
    unsigned s = 0;
#pragma unroll
    for (int i = 0; i < 32; i++) { v[i] = g_count[t * 32 + i]; s += v[i]; }
    sh[t] = s;
    __syncthreads();
    for (int d = 1; d < 1024; d <<= 1) {
        unsigned x = (t >= d) ? sh[t - d] : 0u;
        __syncthreads();
        sh[t] += x;
        __syncthreads();
    }
    unsigned run = sh[t] - s;   // exclusive base for this thread's chunk
#pragma unroll
    for (int i = 0; i < 32; i++) { g_offset[t * 32 + i] = run; run += v[i]; }
}

__global__ void scatter_kernel(const float* __restrict__ pts, int n) {
    int i = blockIdx.x * blockDim.x + threadIdx.x;
    if (i >= n) return;
    float x = pts[3 * i + 0], y = pts[3 * i + 1], z = pts[3 * i + 2];
    unsigned b = bin_of(x, y, z);
    unsigned pos = atomicAdd(&g_offset[b], 1u);
    g_sorted[pos] = make_float4(x, y, z, __int_as_float(i));
}

__device__ __forceinline__ float2 lerp2(float2 a, float2 b, float t) {
    float2 r;
    r.x = a.x + t * (b.x - a.x);
    r.y = a.y + t * (b.y - a.y);
    return r;
}

__global__ __launch_bounds__(256)
void hashgrid_kernel(const float2* __restrict__ tables,
                     float4* __restrict__ out,   // [n, 8] float4 = [n, 32] floats
                     int n)
{
    int s = blockIdx.x * blockDim.x + threadIdx.x;
    if (s >= n) return;

    float4 f = g_sorted[s];
    int orig = __float_as_int(f.w);

    float ax = f.x + 1.0f;
    float ay = f.y + 1.0f;
    float az = f.z + 1.0f;

    const unsigned P0 = 73856093u, P1 = 19349663u, P2 = 83492791u;

    float4* o = out + (size_t)orig * (N_LEVELS / 2);

#pragma unroll
    for (int lp = 0; lp < N_LEVELS / 2; lp++) {
        float4 acc;
#pragma unroll
        for (int h = 0; h < 2; h++) {
            int l = 2 * lp + h;
            // grid = 2/res (compile-time folded); IEEE '/' to bit-match XLA
            float grid = 2.0f / c_res[l];
            float sx = ax / grid;
            float sy = ay / grid;
            float sz = az / grid;

            float fx = floorf(sx), fy = floorf(sy), fz = floorf(sz);
            float wx = sx - fx, wy = sy - fy, wz = sz - fz;

            unsigned ix = (unsigned)(int)fx;
            unsigned iy = (unsigned)(int)fy;
            unsigned iz = (unsigned)(int)fz;

            unsigned hx0 = ix * P0, hx1 = hx0 + P0;
            unsigned hy0 = iy * P1, hy1 = hy0 + P1;
            unsigned hz0 = iz * P2, hz1 = hz0 + P2;

            const float2* t = tables + (size_t)l * TABLE_SZ;

            float2 c000 = __ldg(t + ((hx0 ^ hy0 ^ hz0) & TMASK));
            float2 c001 = __ldg(t + ((hx0 ^ hy0 ^ hz1) & TMASK));
            float2 c010 = __ldg(t + ((hx0 ^ hy1 ^ hz0) & TMASK));
            float2 c011 = __ldg(t + ((hx0 ^ hy1 ^ hz1) & TMASK));
            float2 c100 = __ldg(t + ((hx1 ^ hy0 ^ hz0) & TMASK));
            float2 c101 = __ldg(t + ((hx1 ^ hy0 ^ hz1) & TMASK));
            float2 c110 = __ldg(t + ((hx1 ^ hy1 ^ hz0) & TMASK));
            float2 c111 = __ldg(t + ((hx1 ^ hy1 ^ hz1) & TMASK));

            float2 c00 = lerp2(c000, c001, wz);
            float2 c01 = lerp2(c010, c011, wz);
            float2 c10 = lerp2(c100, c101, wz);
            float2 c11 = lerp2(c110, c111, wz);
            float2 c0  = lerp2(c00, c01, wy);
            float2 c1  = lerp2(c10, c11, wy);
            float2 r   = lerp2(c0, c1, wx);

            if (h == 0) { acc.x = r.x; acc.y = r.y; }
            else        { acc.z = r.x; acc.w = r.y; }
        }
        o[lp] = acc;
    }
}

extern "C" void kernel_launch(void* const* d_in, const int* in_sizes, int n_in,
                              void* d_out, int out_size)
{
    const float*  pts    = (const float*)d_in[0];   // [n, 3]
    const float2* tables = (const float2*)d_in[1];  // [16, 2^19] float2
    float4*       out    = (float4*)d_out;          // [n, 8] float4

    int n = in_sizes[0] / 3;
    if (n > MAXPTS) n = MAXPTS;

    int T = 256;
    int gp = (n + T - 1) / T;

    zero_bins_kernel<<<(NBINS + T - 1) / T, T>>>();
    count_kernel<<<gp, T>>>(pts, n);
    scan_kernel<<<1, 1024>>>();
    scatter_kernel<<<gp, T>>>(pts, n);
    hashgrid_kernel<<<gp, T>>>(tables, out, n);
}